// round 2
// baseline (speedup 1.0000x reference)
#include <cuda_runtime.h>
#include <math.h>
#include <stdint.h>

#define N_NODES 50000
#define IN_DIM 128
#define OUT_DIM 128
#define HEADS 4
#define HEAD_DIM 32
#define N_EDGES 800000
#define LN_EPS 1e-5f
#define NEG_SLOPE 0.2f

// ---------------- scratch (device globals; no allocation allowed) ----------
__device__ float g_h[(size_t)N_NODES * OUT_DIM];      // x @ W
__device__ float g_out[(size_t)N_NODES * OUT_DIM];    // unnormalized message sums
__device__ float g_asrc[N_NODES * HEADS];
__device__ float g_adst[N_NODES * HEADS];
__device__ float g_denom[N_NODES * HEADS];
__device__ int   g_is64;

// ---------------- dtype detection: int64 vs int32 edge_index ---------------
// If edge_index is int64 (little-endian), every odd 32-bit word is a high word
// and equals 0 (values in [0, 50000)). If int32, odd words are random edge ids.
// Only reads the first 1.6M words (6.4MB) = safe under both interpretations.
__global__ void detect_kernel(const int* __restrict__ ei) {
    if (threadIdx.x == 0 && blockIdx.x == 0) {
        int is64 = 1;
        #pragma unroll 1
        for (int i = 0; i < 512; i++) {
            long long w = 1 + 2LL * (long long)i * 1560LL;   // odd indices < 1.6M
            if (ei[w] != 0) { is64 = 0; break; }
        }
        g_is64 = is64;
    }
}

// ---------------- zero accumulators ----------------------------------------
__global__ void zero_kernel() {
    size_t tid    = (size_t)blockIdx.x * blockDim.x + threadIdx.x;
    size_t stride = (size_t)gridDim.x * blockDim.x;
    float4 z = make_float4(0.f, 0.f, 0.f, 0.f);
    float4* o4 = reinterpret_cast<float4*>(g_out);
    for (size_t i = tid; i < (size_t)N_NODES * OUT_DIM / 4; i += stride) o4[i] = z;
    float4* d4 = reinterpret_cast<float4*>(g_denom);
    for (size_t i = tid; i < (size_t)N_NODES * HEADS / 4; i += stride) d4[i] = z;
}

// ---------------- GEMM: h = x @ W  (50000x128 @ 128x128) -------------------
// Block tile: 64 rows x 128 cols. 256 threads, each computes 4 rows x 8 cols
// (two 4-col groups at tc and tc+64 for conflict-free LDS.128 of W).
__global__ __launch_bounds__(256) void gemm_kernel(const float* __restrict__ x,
                                                   const float* __restrict__ W) {
    extern __shared__ float sm[];
    float* Ws = sm;                       // [128][128]
    float* Xs = sm + IN_DIM * OUT_DIM;    // [64][128]
    int t = threadIdx.x;

    const float4* W4 = reinterpret_cast<const float4*>(W);
    float4* Ws4 = reinterpret_cast<float4*>(Ws);
    for (int i = t; i < (IN_DIM * OUT_DIM) / 4; i += 256) Ws4[i] = W4[i];

    int row0 = blockIdx.x * 64;
    float4* Xs4 = reinterpret_cast<float4*>(Xs);
    const float4* x4 = reinterpret_cast<const float4*>(x);
    for (int i = t; i < (64 * IN_DIM) / 4; i += 256) {
        int r = i >> 5;                   // 32 float4 per row
        float4 v = make_float4(0.f, 0.f, 0.f, 0.f);
        if (row0 + r < N_NODES) v = x4[(size_t)(row0 + r) * 32 + (i & 31)];
        Xs4[i] = v;
    }
    __syncthreads();

    int tr = (t >> 4) * 4;                // 0..60
    int tc = (t & 15) * 4;                // 0..60 ; second group at tc+64
    float acc0[4][4] = {};
    float acc1[4][4] = {};

    #pragma unroll 8
    for (int k = 0; k < IN_DIM; k++) {
        float4 w0 = *reinterpret_cast<const float4*>(&Ws[k * 128 + tc]);
        float4 w1 = *reinterpret_cast<const float4*>(&Ws[k * 128 + tc + 64]);
        #pragma unroll
        for (int i = 0; i < 4; i++) {
            float xv = Xs[(tr + i) * 128 + k];
            acc0[i][0] += xv * w0.x; acc0[i][1] += xv * w0.y;
            acc0[i][2] += xv * w0.z; acc0[i][3] += xv * w0.w;
            acc1[i][0] += xv * w1.x; acc1[i][1] += xv * w1.y;
            acc1[i][2] += xv * w1.z; acc1[i][3] += xv * w1.w;
        }
    }

    #pragma unroll
    for (int i = 0; i < 4; i++) {
        int row = row0 + tr + i;
        if (row < N_NODES) {
            float4 v0 = make_float4(acc0[i][0], acc0[i][1], acc0[i][2], acc0[i][3]);
            float4 v1 = make_float4(acc1[i][0], acc1[i][1], acc1[i][2], acc1[i][3]);
            *reinterpret_cast<float4*>(&g_h[(size_t)row * 128 + tc])      = v0;
            *reinterpret_cast<float4*>(&g_h[(size_t)row * 128 + tc + 64]) = v1;
        }
    }
}

// ---------------- attention logits: a_src[n,h], a_dst[n,h] -----------------
// One warp per node; lane handles 4 contiguous channels; 8-lane segmented
// reduction per head.
__global__ __launch_bounds__(256) void att_kernel(const float* __restrict__ att_src,
                                                  const float* __restrict__ att_dst) {
    int node = (int)(((size_t)blockIdx.x * blockDim.x + threadIdx.x) >> 5);
    int lane = threadIdx.x & 31;
    if (node >= N_NODES) return;

    float4 hv = *reinterpret_cast<const float4*>(&g_h[(size_t)node * 128 + lane * 4]);
    float4 s4 = __ldg(reinterpret_cast<const float4*>(att_src + lane * 4));
    float4 d4 = __ldg(reinterpret_cast<const float4*>(att_dst + lane * 4));
    float ps = hv.x * s4.x + hv.y * s4.y + hv.z * s4.z + hv.w * s4.w;
    float pd = hv.x * d4.x + hv.y * d4.y + hv.z * d4.z + hv.w * d4.w;
    ps += __shfl_xor_sync(0xffffffffu, ps, 1);
    ps += __shfl_xor_sync(0xffffffffu, ps, 2);
    ps += __shfl_xor_sync(0xffffffffu, ps, 4);
    pd += __shfl_xor_sync(0xffffffffu, pd, 1);
    pd += __shfl_xor_sync(0xffffffffu, pd, 2);
    pd += __shfl_xor_sync(0xffffffffu, pd, 4);
    if ((lane & 7) == 0) {
        int head = lane >> 3;
        g_asrc[node * 4 + head] = ps;
        g_adst[node * 4 + head] = pd;
    }
}

// ---------------- edge pass: single pass, deferred normalization -----------
// One warp processes 32 edges: lane i preloads edge (base+i)'s indices, then
// the warp iterates the 32 edges. Per edge: lane -> 4 channels (float4),
// red.global.add.v4.f32 into out[dst]; lane 0 adds the 4 head exps to denom.
__global__ __launch_bounds__(256) void edge_kernel(const int* __restrict__ ei) {
    const int lane = threadIdx.x & 31;
    const int gw = (int)(((size_t)blockIdx.x * blockDim.x + threadIdx.x) >> 5);
    const int nw = (gridDim.x * blockDim.x) >> 5;
    const int is64 = g_is64;
    const int head = lane >> 3;

    for (int base = gw * 32; base < N_EDGES; base += nw * 32) {
        int e = base + lane;
        int s_r = 0, d_r = 0;
        if (e < N_EDGES) {
            if (is64) { s_r = ei[2 * e]; d_r = ei[2 * (N_EDGES + e)]; }
            else      { s_r = ei[e];     d_r = ei[N_EDGES + e]; }
        }
        int cnt = min(32, N_EDGES - base);
        for (int i = 0; i < cnt; i++) {
            int s = __shfl_sync(0xffffffffu, s_r, i);
            int d = __shfl_sync(0xffffffffu, d_r, i);

            float4 as = __ldg(reinterpret_cast<const float4*>(g_asrc + s * 4));
            float4 ad = __ldg(reinterpret_cast<const float4*>(g_adst + d * 4));
            float e0 = as.x + ad.x, e1 = as.y + ad.y, e2 = as.z + ad.z, e3 = as.w + ad.w;
            e0 = e0 > 0.f ? e0 : NEG_SLOPE * e0;
            e1 = e1 > 0.f ? e1 : NEG_SLOPE * e1;
            e2 = e2 > 0.f ? e2 : NEG_SLOPE * e2;
            e3 = e3 > 0.f ? e3 : NEG_SLOPE * e3;
            float eh  = head == 0 ? e0 : (head == 1 ? e1 : (head == 2 ? e2 : e3));
            float exh = __expf(eh);

            float4 hv = __ldg(reinterpret_cast<const float4*>(
                g_h + (size_t)s * 128 + lane * 4));
            float* outp = g_out + (size_t)d * 128 + lane * 4;
            asm volatile("red.global.add.v4.f32 [%0], {%1,%2,%3,%4};"
                         :: "l"(outp), "f"(hv.x * exh), "f"(hv.y * exh),
                            "f"(hv.z * exh), "f"(hv.w * exh)
                         : "memory");

            // denom: head exps live in lanes 0, 8, 16, 24
            float x1 = __shfl_sync(0xffffffffu, exh, 8);
            float x2 = __shfl_sync(0xffffffffu, exh, 16);
            float x3 = __shfl_sync(0xffffffffu, exh, 24);
            if (lane == 0) {
                asm volatile("red.global.add.v4.f32 [%0], {%1,%2,%3,%4};"
                             :: "l"(g_denom + (size_t)d * 4), "f"(exh), "f"(x1),
                                "f"(x2), "f"(x3)
                             : "memory");
            }
        }
    }
}

// ---------------- node epilogue: self-loop + normalize + LN + GELU ---------
__global__ __launch_bounds__(256) void node_kernel(const float* __restrict__ x,
                                                   const float* __restrict__ bias,
                                                   const float* __restrict__ gamma,
                                                   const float* __restrict__ beta,
                                                   float* __restrict__ out) {
    int n = (int)(((size_t)blockIdx.x * blockDim.x + threadIdx.x) >> 5);
    int lane = threadIdx.x & 31;
    if (n >= N_NODES) return;
    int head = lane >> 3;

    // self-loop attention exp per head
    float4 as = *reinterpret_cast<const float4*>(g_asrc + (size_t)n * 4);
    float4 ad = *reinterpret_cast<const float4*>(g_adst + (size_t)n * 4);
    float e0 = as.x + ad.x, e1 = as.y + ad.y, e2 = as.z + ad.z, e3 = as.w + ad.w;
    e0 = e0 > 0.f ? e0 : NEG_SLOPE * e0;
    e1 = e1 > 0.f ? e1 : NEG_SLOPE * e1;
    e2 = e2 > 0.f ? e2 : NEG_SLOPE * e2;
    e3 = e3 > 0.f ? e3 : NEG_SLOPE * e3;
    float ex0 = __expf(e0), ex1 = __expf(e1), ex2 = __expf(e2), ex3 = __expf(e3);

    float4 dn = *reinterpret_cast<const float4*>(g_denom + (size_t)n * 4);
    float den = head == 0 ? dn.x + ex0 : (head == 1 ? dn.y + ex1
              : (head == 2 ? dn.z + ex2 : dn.w + ex3));
    float exh = head == 0 ? ex0 : (head == 1 ? ex1 : (head == 2 ? ex2 : ex3));
    float inv = 1.f / den;

    float4 acc = *reinterpret_cast<const float4*>(g_out + (size_t)n * 128 + lane * 4);
    float4 hv  = *reinterpret_cast<const float4*>(g_h   + (size_t)n * 128 + lane * 4);
    float4 b4  = __ldg(reinterpret_cast<const float4*>(bias + lane * 4));

    float v0 = (acc.x + hv.x * exh) * inv + b4.x;
    float v1 = (acc.y + hv.y * exh) * inv + b4.y;
    float v2 = (acc.z + hv.z * exh) * inv + b4.z;
    float v3 = (acc.w + hv.w * exh) * inv + b4.w;

    // LayerNorm over 128 channels (warp allreduce; 4 values/lane)
    float s = v0 + v1 + v2 + v3;
    #pragma unroll
    for (int o = 16; o > 0; o >>= 1) s += __shfl_xor_sync(0xffffffffu, s, o);
    float mu = s * (1.f / 128.f);
    float d0 = v0 - mu, d1 = v1 - mu, d2 = v2 - mu, d3 = v3 - mu;
    float q = d0 * d0 + d1 * d1 + d2 * d2 + d3 * d3;
    #pragma unroll
    for (int o = 16; o > 0; o >>= 1) q += __shfl_xor_sync(0xffffffffu, q, o);
    float rstd = rsqrtf(q * (1.f / 128.f) + LN_EPS);

    float4 gm = __ldg(reinterpret_cast<const float4*>(gamma + lane * 4));
    float4 bt = __ldg(reinterpret_cast<const float4*>(beta + lane * 4));
    float4 xv = *reinterpret_cast<const float4*>(x + (size_t)n * 128 + lane * 4);

    float h0 = d0 * rstd * gm.x + bt.x + xv.x;
    float h1 = d1 * rstd * gm.y + bt.y + xv.y;
    float h2 = d2 * rstd * gm.z + bt.z + xv.z;
    float h3 = d3 * rstd * gm.w + bt.w + xv.w;

    const float k = 0.70710678118654752f;
    float4 r;
    r.x = 0.5f * h0 * (1.f + erff(h0 * k));
    r.y = 0.5f * h1 * (1.f + erff(h1 * k));
    r.z = 0.5f * h2 * (1.f + erff(h2 * k));
    r.w = 0.5f * h3 * (1.f + erff(h3 * k));
    *reinterpret_cast<float4*>(out + (size_t)n * 128 + lane * 4) = r;
}

// ---------------- launch ----------------------------------------------------
extern "C" void kernel_launch(void* const* d_in, const int* in_sizes, int n_in,
                              void* d_out, int out_size) {
    const float* x       = (const float*)d_in[0];
    const int*   ei      = (const int*)d_in[1];   // int32 or int64 (detected)
    const float* W       = (const float*)d_in[2];
    const float* att_src = (const float*)d_in[3];
    const float* att_dst = (const float*)d_in[4];
    const float* bias    = (const float*)d_in[5];
    const float* gamma   = (const float*)d_in[6];
    const float* beta    = (const float*)d_in[7];
    float* out = (float*)d_out;

    cudaFuncSetAttribute(gemm_kernel, cudaFuncAttributeMaxDynamicSharedMemorySize,
                         98304);

    detect_kernel<<<1, 1>>>(ei);
    zero_kernel<<<512, 256>>>();
    gemm_kernel<<<(N_NODES + 63) / 64, 256, 98304>>>(x, W);
    att_kernel<<<(N_NODES + 7) / 8, 256>>>(att_src, att_dst);
    edge_kernel<<<3125, 256>>>(ei);
    node_kernel<<<(N_NODES + 7) / 8, 256>>>(x, bias, gamma, beta, out);
}